// round 5
// baseline (speedup 1.0000x reference)
#include <cuda_runtime.h>

#define B_ 16
#define A_ 5
#define C_ 512
#define HW_ 256
#define NC 4
#define CCHUNK 32

// out[(i*B+b)] = local[(i*B+b)] + sum_{j != i, j<n, i<n} warp(local[(j*B+b)], trans[b,i,j])
// warp = bilinear grid_sample chained twice (rotation, then constant translation),
// zero padding, align_corners=False. Geometry channel-invariant -> register tap
// tables; tiles channel-vectorized float4; tile fills via cp.async, double
// buffered and software-pipelined one chunk ahead (2 barriers/chunk).

__device__ __forceinline__ void cp_async4(void* smem_dst, const void* gsrc) {
    unsigned s = (unsigned)__cvta_generic_to_shared(smem_dst);
    asm volatile("cp.async.ca.shared.global [%0], [%1], 4;\n" :: "r"(s), "l"(gsrc));
}
__device__ __forceinline__ void cp_commit() {
    asm volatile("cp.async.commit_group;\n" ::: "memory");
}
__device__ __forceinline__ void cp_wait_all() {
    asm volatile("cp.async.wait_group 0;\n" ::: "memory");
}

__global__ __launch_bounds__(256, 2)
void fuse_kernel(const float* __restrict__ feat,
                 const float* __restrict__ trans,
                 const int* __restrict__ nag,
                 float* __restrict__ out)
{
    __shared__ float4 tileA[2][4][257];   // double-buffered source tiles (4 ch/pixel)
    __shared__ float4 tileR[2][4][257];   // double-buffered rotation intermediates

    const int b  = blockIdx.z;
    const int i  = blockIdx.y;
    const int c0 = blockIdx.x * CCHUNK;
    const int t  = threadIdx.x;
    const int x  = t & 15;
    const int y  = t >> 4;

    const int n = nag[b * A_];            // num_agent_tensor[b, 0]
    const bool active = (i < n) && (n > 1);

    const size_t base = ((size_t)(i * B_ + b) * C_ + c0) * HW_;
    const float* __restrict__ local = feat + base;
    float* __restrict__ outp        = out  + base;

    // normalized pixel coords (align_corners=False)
    const float xs = (2.f * (float)x + 1.f) / 16.f - 1.f;
    const float ys = (2.f * (float)y + 1.f) / 16.f - 1.f;

    // Per-neighbor tap metadata (channel-invariant).
    float    wA[4][4], wB[4][4];
    unsigned pA[4], pB[4];                // 4 byte-indices packed per table
    const float* srcp[4];
    bool valid[4];

    #pragma unroll
    for (int jj = 0; jj < 4; jj++) {
        const int j = jj + (jj >= i ? 1 : 0);          // skip j == i
        const bool v = active && (j < n);
        valid[jj] = v;
        srcp[jj]  = feat + ((size_t)(j * B_ + b) * C_ + c0) * HW_;
        pA[jj] = 0u; pB[jj] = 0u;
        #pragma unroll
        for (int m = 0; m < 4; m++) { wA[jj][m] = 0.f; wB[jj][m] = 0.f; }
        if (v) {
            const float* T = trans + (((size_t)(b * A_ + i) * A_ + j) * 16);
            const float t00 = T[0], t01 = T[1], t03 = T[3];
            const float t10 = T[4], t11 = T[5], t13 = T[7];

            // ---- stage 1: rotation grid ----
            const float gx = t00 * xs + t01 * ys;
            const float gy = t10 * xs + t11 * ys;
            const float ix = ((gx + 1.f) * 16.f - 1.f) * 0.5f;
            const float iy = ((gy + 1.f) * 16.f - 1.f) * 0.5f;
            const float x0f = floorf(ix), y0f = floorf(iy);
            const float fx = ix - x0f,  fy = iy - y0f;
            const int x0 = (int)x0f, y0 = (int)y0f;
            #pragma unroll
            for (int m = 0; m < 4; m++) {
                const int dx = m & 1, dy = m >> 1;
                const int xi = x0 + dx, yi = y0 + dy;
                const float w = (dx ? fx : 1.f - fx) * (dy ? fy : 1.f - fy);
                const bool in = (xi >= 0) & (xi < 16) & (yi >= 0) & (yi < 16);
                wA[jj][m] = in ? w : 0.f;
                pA[jj]  |= (unsigned)(in ? (yi * 16 + xi) : 0) << (8 * m);
            }

            // ---- stage 2: translation grid ----
            const float xt = t03 * (1.f / 32.f);      // 4*T03/128
            const float yt = -t13 * (1.f / 32.f);
            const float ix2 = ((xs + xt + 1.f) * 16.f - 1.f) * 0.5f;
            const float iy2 = ((ys + yt + 1.f) * 16.f - 1.f) * 0.5f;
            const float x20f = floorf(ix2), y20f = floorf(iy2);
            const float fx2 = ix2 - x20f,  fy2 = iy2 - y20f;
            const int x20 = (int)x20f, y20 = (int)y20f;
            #pragma unroll
            for (int m = 0; m < 4; m++) {
                const int dx = m & 1, dy = m >> 1;
                const int xi = x20 + dx, yi = y20 + dy;
                const float w = (dx ? fx2 : 1.f - fx2) * (dy ? fy2 : 1.f - fy2);
                const bool in = (xi >= 0) & (xi < 16) & (yi >= 0) & (yi < 16);
                wB[jj][m] = in ? w : 0.f;
                pB[jj]  |= (unsigned)(in ? (yi * 16 + xi) : 0) << (8 * m);
            }
        }
    }

    // ---- prologue: async-fill chunk 0 into buffer 0 ----
    #pragma unroll
    for (int jj = 0; jj < 4; jj++) {
        if (valid[jj]) {
            const float* src = srcp[jj];
            float* dst = &tileA[0][jj][t].x;
            #pragma unroll
            for (int k = 0; k < NC; k++)
                cp_async4(dst + k, src + (size_t)k * HW_ + t);
        }
    }
    cp_commit();

    int p = 0;
    for (int g = 0; g < CCHUNK; g += NC, p ^= 1) {
        float4 acc;
        acc.x = local[(size_t)(g + 0) * HW_ + t];
        acc.y = local[(size_t)(g + 1) * HW_ + t];
        acc.z = local[(size_t)(g + 2) * HW_ + t];
        acc.w = local[(size_t)(g + 3) * HW_ + t];

        cp_wait_all();
        __syncthreads();                  // fills for chunk g visible to all

        // issue fills for chunk g+1 into the other buffer (overlaps gathers below)
        if (g + NC < CCHUNK) {
            #pragma unroll
            for (int jj = 0; jj < 4; jj++) {
                if (valid[jj]) {
                    const float* src = srcp[jj] + (size_t)(g + NC) * HW_;
                    float* dst = &tileA[p ^ 1][jj][t].x;
                    #pragma unroll
                    for (int k = 0; k < NC; k++)
                        cp_async4(dst + k, src + (size_t)k * HW_ + t);
                }
            }
        }
        cp_commit();

        // stage 1: rotation sample -> R tiles (one LDS.128 per tap, 4 channels)
        #pragma unroll
        for (int jj = 0; jj < 4; jj++) {
            if (valid[jj]) {
                const float4 v0 = tileA[p][jj][(pA[jj]      ) & 255];
                const float4 v1 = tileA[p][jj][(pA[jj] >>  8) & 255];
                const float4 v2 = tileA[p][jj][(pA[jj] >> 16) & 255];
                const float4 v3 = tileA[p][jj][(pA[jj] >> 24) & 255];
                const float w0 = wA[jj][0], w1 = wA[jj][1], w2 = wA[jj][2], w3 = wA[jj][3];
                float4 r;
                r.x = w0 * v0.x + w1 * v1.x + w2 * v2.x + w3 * v3.x;
                r.y = w0 * v0.y + w1 * v1.y + w2 * v2.y + w3 * v3.y;
                r.z = w0 * v0.z + w1 * v1.z + w2 * v2.z + w3 * v3.z;
                r.w = w0 * v0.w + w1 * v1.w + w2 * v2.w + w3 * v3.w;
                tileR[p][jj][t] = r;
            }
        }
        __syncthreads();                  // tileR[p] ready

        // stage 2: translation sample -> accumulate
        #pragma unroll
        for (int jj = 0; jj < 4; jj++) {
            if (valid[jj]) {
                const float4 v0 = tileR[p][jj][(pB[jj]      ) & 255];
                const float4 v1 = tileR[p][jj][(pB[jj] >>  8) & 255];
                const float4 v2 = tileR[p][jj][(pB[jj] >> 16) & 255];
                const float4 v3 = tileR[p][jj][(pB[jj] >> 24) & 255];
                const float w0 = wB[jj][0], w1 = wB[jj][1], w2 = wB[jj][2], w3 = wB[jj][3];
                acc.x += w0 * v0.x + w1 * v1.x + w2 * v2.x + w3 * v3.x;
                acc.y += w0 * v0.y + w1 * v1.y + w2 * v2.y + w3 * v3.y;
                acc.z += w0 * v0.z + w1 * v1.z + w2 * v2.z + w3 * v3.z;
                acc.w += w0 * v0.w + w1 * v1.w + w2 * v2.w + w3 * v3.w;
            }
        }

        outp[(size_t)(g + 0) * HW_ + t] = acc.x;
        outp[(size_t)(g + 1) * HW_ + t] = acc.y;
        outp[(size_t)(g + 2) * HW_ + t] = acc.z;
        outp[(size_t)(g + 3) * HW_ + t] = acc.w;
    }
}

extern "C" void kernel_launch(void* const* d_in, const int* in_sizes, int n_in,
                              void* d_out, int out_size)
{
    const float* feat  = (const float*)d_in[0];   // [A*B, C, H, W] f32
    const float* trans = (const float*)d_in[1];   // [B, A, A, 4, 4] f32
    const int*   nag   = (const int*)d_in[2];     // [B, A] int32
    float* out = (float*)d_out;                   // [A*B, C, H, W] f32

    dim3 grid(C_ / CCHUNK, A_, B_);
    fuse_kernel<<<grid, 256>>>(feat, trans, nag, out);
}